// round 1
// baseline (speedup 1.0000x reference)
#include <cuda_runtime.h>
#include <math.h>

#define TT 64          // sequence length
#define CC 128         // embed dim
#define HD 32          // head dim
#define NC 96          // 3*HD
#define XS_STRIDE 129  // x smem row stride (odd -> conflict-free)
#define QKV_STRIDE 97  // qkv smem row stride (odd)
#define SC_STRIDE 65   // scores smem row stride (odd)
#define NTHREADS 256

// smem: xs [64][129] floats (reused as scores [64][65]) + qkv [64][97]
#define SMEM_FLOATS (TT * XS_STRIDE + TT * QKV_STRIDE)

__global__ __launch_bounds__(NTHREADS, 3)
void head_attn_kernel(const float* __restrict__ x,
                      const float* __restrict__ Wq,
                      const float* __restrict__ Wk,
                      const float* __restrict__ Wv,
                      float* __restrict__ out) {
    extern __shared__ float smem[];
    float* xs  = smem;                     // [64][129]; later scores [64][65]
    float* qkv = smem + TT * XS_STRIDE;    // [64][97]: cols 0-31 q, 32-63 k, 64-95 v

    const int tid = threadIdx.x;
    const int b   = blockIdx.x;
    const float* xb = x + (size_t)b * (TT * CC);

    // ---------------- Phase 0: stage x into smem ----------------
    // global float4 loads, scalar STS (stride 129 breaks 16B row alignment)
    for (int i = tid; i < (TT * CC) / 4; i += NTHREADS) {
        float4 v4 = reinterpret_cast<const float4*>(xb)[i];
        int idx = i * 4;
        int r = idx >> 7;        // /128
        int c = idx & 127;
        float* dst = xs + r * XS_STRIDE + c;
        dst[0] = v4.x; dst[1] = v4.y; dst[2] = v4.z; dst[3] = v4.w;
    }
    __syncthreads();

    // ---------------- Phase 1: fused QKV projection ----------------
    // [64,128] @ [128,96] -> qkv[64,96]. Register tile: 4 rows x 6 cols.
    // Lanes vary over col-tile -> x LDS is a 2-address broadcast (conflict-free
    // with stride 129); W comes via __ldg (L1-resident, coalesced per row).
    {
        const int ct = tid & 15;     // 16 col tiles * 6 cols = 96
        const int rt = tid >> 4;     // 16 row tiles * 4 rows = 64
        const int c0 = ct * 6;
        const int r0 = rt * 4;

        const float* wp[6];
        #pragma unroll
        for (int j = 0; j < 6; j++) {
            int c = c0 + j;
            wp[j] = (c < 32) ? (Wq + c) : (c < 64) ? (Wk + (c - 32)) : (Wv + (c - 64));
        }

        float acc[4][6];
        #pragma unroll
        for (int i = 0; i < 4; i++)
            #pragma unroll
            for (int j = 0; j < 6; j++) acc[i][j] = 0.0f;

        #pragma unroll 4
        for (int d = 0; d < CC; d++) {
            float xv[4];
            #pragma unroll
            for (int i = 0; i < 4; i++) xv[i] = xs[(r0 + i) * XS_STRIDE + d];
            float wv[6];
            #pragma unroll
            for (int j = 0; j < 6; j++) wv[j] = __ldg(wp[j] + d * HD);
            #pragma unroll
            for (int i = 0; i < 4; i++)
                #pragma unroll
                for (int j = 0; j < 6; j++) acc[i][j] = fmaf(xv[i], wv[j], acc[i][j]);
        }

        #pragma unroll
        for (int i = 0; i < 4; i++)
            #pragma unroll
            for (int j = 0; j < 6; j++)
                qkv[(r0 + i) * QKV_STRIDE + c0 + j] = acc[i][j];
    }
    __syncthreads();

    // ---------------- Phase 2: scores = scale * q @ k^T ----------------
    // 4x4 register tiles over [64,64]; skip fully-masked tiles (causal).
    // scores overlay the xs region (x is dead now).
    {
        const int ct = tid & 15;     // 16 col tiles * 4
        const int rt = tid >> 4;     // 16 row tiles * 4
        const int c0 = ct * 4;
        const int r0 = rt * 4;
        float* sc = xs;

        if (c0 <= r0 + 3) {
            float acc[4][4];
            #pragma unroll
            for (int i = 0; i < 4; i++)
                #pragma unroll
                for (int j = 0; j < 4; j++) acc[i][j] = 0.0f;

            #pragma unroll 4
            for (int d = 0; d < HD; d++) {
                float qv[4], kv[4];
                #pragma unroll
                for (int i = 0; i < 4; i++) qv[i] = qkv[(r0 + i) * QKV_STRIDE + d];
                #pragma unroll
                for (int j = 0; j < 4; j++) kv[j] = qkv[(c0 + j) * QKV_STRIDE + 32 + d];
                #pragma unroll
                for (int i = 0; i < 4; i++)
                    #pragma unroll
                    for (int j = 0; j < 4; j++) acc[i][j] = fmaf(qv[i], kv[j], acc[i][j]);
            }

            const float scale = 0.17677669529663687f;  // 1/sqrt(32)
            #pragma unroll
            for (int i = 0; i < 4; i++)
                #pragma unroll
                for (int j = 0; j < 4; j++)
                    sc[(r0 + i) * SC_STRIDE + c0 + j] = acc[i][j] * scale;
        }
    }
    __syncthreads();

    // ---------------- Phase 3: causal softmax, one warp per row ----------------
    {
        const int w    = tid >> 5;
        const int lane = tid & 31;
        for (int r = w; r < TT; r += 8) {
            float* row = xs + r * SC_STRIDE;
            bool v0 = (lane <= r);
            bool v1 = (lane + 32 <= r);
            float s0 = v0 ? row[lane]      : -1e30f;
            float s1 = v1 ? row[lane + 32] : -1e30f;
            float m = fmaxf(s0, s1);
            #pragma unroll
            for (int off = 16; off > 0; off >>= 1)
                m = fmaxf(m, __shfl_xor_sync(0xffffffffu, m, off));
            float e0 = v0 ? __expf(s0 - m) : 0.0f;
            float e1 = v1 ? __expf(s1 - m) : 0.0f;
            float sum = e0 + e1;
            #pragma unroll
            for (int off = 16; off > 0; off >>= 1)
                sum += __shfl_xor_sync(0xffffffffu, sum, off);
            float inv = 1.0f / sum;
            row[lane]      = e0 * inv;
            row[lane + 32] = e1 * inv;
        }
    }
    __syncthreads();

    // ---------------- Phase 4: out = probs @ v ----------------
    // 2 rows x 4 head-cols per thread; causal truncation of the c loop.
    {
        const int ct = tid & 7;      // 8 col tiles * 4 = 32
        const int rt = tid >> 3;     // 32 row tiles * 2 = 64
        const int h0 = ct * 4;
        const int r0 = rt * 2;

        float acc0[4] = {0.f, 0.f, 0.f, 0.f};
        float acc1[4] = {0.f, 0.f, 0.f, 0.f};
        const int cmax = r0 + 1;     // probs are exactly 0 beyond row index

        for (int c = 0; c <= cmax; c++) {
            float p0 = xs[r0 * SC_STRIDE + c];
            float p1 = xs[(r0 + 1) * SC_STRIDE + c];
            const float* vr = qkv + c * QKV_STRIDE + 64 + h0;
            #pragma unroll
            for (int j = 0; j < 4; j++) {
                float vv = vr[j];
                acc0[j] = fmaf(p0, vv, acc0[j]);
                acc1[j] = fmaf(p1, vv, acc1[j]);
            }
        }

        float* ob = out + (size_t)b * (TT * HD);
        float4 o0 = make_float4(acc0[0], acc0[1], acc0[2], acc0[3]);
        float4 o1 = make_float4(acc1[0], acc1[1], acc1[2], acc1[3]);
        *reinterpret_cast<float4*>(ob + r0 * HD + h0)       = o0;
        *reinterpret_cast<float4*>(ob + (r0 + 1) * HD + h0) = o1;
    }
}

extern "C" void kernel_launch(void* const* d_in, const int* in_sizes, int n_in,
                              void* d_out, int out_size) {
    const float* x  = (const float*)d_in[0];
    const float* Wq = (const float*)d_in[1];
    const float* Wk = (const float*)d_in[2];
    const float* Wv = (const float*)d_in[3];
    float* out = (float*)d_out;

    const int B = in_sizes[0] / (TT * CC);   // 4096
    const size_t smem_bytes = SMEM_FLOATS * sizeof(float);

    static_assert(SMEM_FLOATS * sizeof(float) < 228 * 1024, "smem budget");
    cudaFuncSetAttribute(head_attn_kernel,
                         cudaFuncAttributeMaxDynamicSharedMemorySize,
                         (int)smem_bytes);

    head_attn_kernel<<<B, NTHREADS, smem_bytes>>>(x, Wq, Wk, Wv, out);
}